// round 11
// baseline (speedup 1.0000x reference)
#include <cuda_runtime.h>
#include <math.h>

// Problem constants (fixed by the reference)
#define N_K        16
#define C_CAT      136          // 16*17/2 upper-tri pairs
#define C_PAD      160          // padded to 32*5 for a uniform unrolled loop
#define DIM        64
#define MU_PITCH   68           // DIM + 4 pad: rows 16B-aligned (68*4 = 272)
#define NROWS      8192         // 512 * 16
#define ROWS_PER_BLK 16         // 4 warps x 4 rows
#define NTHR       128
#define MAIN_BLOCKS (NROWS / ROWS_PER_BLK)   // 512

#define LOG2PI_F   1.8378770664093453f
#define LN2_F      0.6931471805599453f
// Phi-tanh approx: Phi(x) ~= 0.5*(1+tanh(C1*x + C3*x^3))
#define PHI_C1     0.7978845608028654f
#define PHI_C3     0.03567740813712f

// ---- device scratch (static globals; no allocation) ----
__device__ float  d_partials[MAIN_BLOCKS];
__device__ unsigned int d_counter = 0;

__device__ __forceinline__ float tanh_approx(float x) {
    float r; asm("tanh.approx.f32 %0, %1;" : "=f"(r) : "f"(x)); return r;
}

// ---------------------------------------------------------------------------
// SINGLE fused kernel. 16 rows/block (128 thr), FOUR rows per warp.
// Cheap per-block prologue (warp-local softmax, Gram-based category constants),
// 20-chain ILP hot loop, last-block-done deterministic finalize.
// Diagonal pairs encoded as heavy categories (k1=0, recip=0 -> nu=0; s=20 ->
// tanh(u1)=1, tanh(u2)=0 -> D=1; base=lp). Slots [136,160) are -inf padding.
// ---------------------------------------------------------------------------
__global__ __launch_bounds__(NTHR) void fused_kernel(const float* __restrict__ z,
                                                     const float* __restrict__ pi,
                                                     const float* __restrict__ mu,
                                                     float* __restrict__ out)
{
    __shared__ float  mu_t[N_K][MU_PITCH];          // transposed mu
    __shared__ float  z_s [ROWS_PER_BLK][DIM];      // 4 KB
    __shared__ float4 c4_s[C_PAD];                  // {k1, 0.5*mB2, recip, s}
    __shared__ float2 cb_s[C_PAD];                  // {base, bitcast(A|B<<8)}
    __shared__ float  rowres[ROWS_PER_BLK];
    __shared__ float  red[NTHR];
    __shared__ int    s_is_last;

    const int t = threadIdx.x;
    const int w = t >> 5;        // warp 0..3; handles rows 4w..4w+3
    const int l = t & 31;

    // prefetch 4 rows' z into registers immediately (DRAM latency overlaps
    // the whole prologue)
    const int row0 = blockIdx.x * ROWS_PER_BLK;
    const float* zp = z + (row0 + 4 * w) * DIM;
    float zr[4][2];
    #pragma unroll
    for (int r = 0; r < 4; ++r) {
        zr[r][0] = zp[r * DIM + l];
        zr[r][1] = zp[r * DIM + l + 32];
    }

    // stage mu transposed
    for (int i = t; i < DIM * N_K; i += NTHR) {
        const int d = i >> 4, k = i & 15;           // mu is [d][k]
        mu_t[k][d] = mu[i];
    }
    // stage this warp's z rows
    #pragma unroll
    for (int r = 0; r < 4; ++r) {
        z_s[4 * w + r][l]      = zr[r][0];
        z_s[4 * w + r][l + 32] = zr[r][1];
    }
    // padding category slots
    if (t < C_PAD - C_CAT) {
        c4_s[C_CAT + t] = make_float4(0.f, 0.f, 0.f, 20.f);
        cb_s[C_CAT + t] = make_float2(-1e30f, __int_as_float(0));
    }

    // warp-local softmax denominator over the 136 pi logits
    const float v0 = pi[l], v1 = pi[l + 32], v2 = pi[l + 64], v3 = pi[l + 96];
    const float v4 = (l < 8) ? pi[128 + l] : -INFINITY;
    float mx = fmaxf(fmaxf(fmaxf(v0, v1), fmaxf(v2, v3)), v4);
    #pragma unroll
    for (int o = 16; o; o >>= 1) mx = fmaxf(mx, __shfl_xor_sync(0xffffffffu, mx, o));
    float sm = __expf(v0 - mx) + __expf(v1 - mx) + __expf(v2 - mx) + __expf(v3 - mx)
             + ((l < 8) ? __expf(v4 - mx) : 0.f);
    #pragma unroll
    for (int o = 16; o; o >>= 1) sm += __shfl_xor_sync(0xffffffffu, sm, o);
    const float lgden = mx + __logf(sm);            // log softmax denominator

    __syncthreads();                                 // mu_t ready

    // ---- per-category constants (threads cover 136 categories in 2 passes) ----
    for (int c = t; c < C_CAT; c += NTHR) {
        int A = 0, rem = c;
        while (rem >= (N_K - A)) { rem -= (N_K - A); ++A; }
        const int B = A + rem;

        const float4* ma = (const float4*)&mu_t[A][0];
        const float4* mb = (const float4*)&mu_t[B][0];
        float aa0=0.f, aa1=0.f, aa2=0.f, aa3=0.f;
        float ab0=0.f, ab1=0.f, ab2=0.f, ab3=0.f;
        float bb0=0.f, bb1=0.f, bb2=0.f, bb3=0.f;
        #pragma unroll
        for (int j = 0; j < 16; ++j) {
            const float4 fa = ma[j];
            const float4 fb = mb[j];
            aa0 = fmaf(fa.x, fa.x, aa0); aa1 = fmaf(fa.y, fa.y, aa1);
            aa2 = fmaf(fa.z, fa.z, aa2); aa3 = fmaf(fa.w, fa.w, aa3);
            ab0 = fmaf(fa.x, fb.x, ab0); ab1 = fmaf(fa.y, fb.y, ab1);
            ab2 = fmaf(fa.z, fb.z, ab2); ab3 = fmaf(fa.w, fb.w, ab3);
            bb0 = fmaf(fb.x, fb.x, bb0); bb1 = fmaf(fb.y, fb.y, bb1);
            bb2 = fmaf(fb.z, fb.z, bb2); bb3 = fmaf(fb.w, fb.w, bb3);
        }
        const float GAA = (aa0 + aa1) + (aa2 + aa3);
        const float GAB = (ab0 + ab1) + (ab2 + ab3);
        const float GBB = (bb0 + bb1) + (bb2 + bb3);

        const float invsig = (GAA - 2.0f * GAB) + GBB;
        const float lp = -32.0f * LOG2PI_F + (__ldg(&pi[c]) - lgden);

        float base, recip, s, k1;
        if (A == B) {                        // diag: inv_sig == 0 exactly
            base = lp; recip = 0.f; s = 20.f; k1 = 0.f;
        } else {
            const float clip_is = fminf(fmaxf(invsig, 1e-12f), 1e30f);
            s     = sqrtf(clip_is);
            base  = lp + 0.5f * (LOG2PI_F - __logf(clip_is)) - LN2_F;
            recip = 1.0f / invsig;
            k1    = GBB - GAB;               // dot(alpha, mu_B)
        }
        c4_s[c] = make_float4(k1, 0.5f * GBB, recip, s);
        cb_s[c] = make_float2(base, __int_as_float(A | (B << 8)));
    }
    __syncthreads();                                 // constants ready

    // hoist this lane's 5 category-constant sets (shared by all 4 rows)
    float4 c4r[5];
    float2 cbr[5];
    #pragma unroll
    for (int i = 0; i < 5; ++i) {
        c4r[i] = c4_s[l + 32 * i];
        cbr[i] = cb_s[l + 32 * i];
    }

    // 0.5*|z|^2, 4 rows interleaved through one butterfly
    float p[4];
    #pragma unroll
    for (int r = 0; r < 4; ++r)
        p[r] = zr[r][0] * zr[r][0] + zr[r][1] * zr[r][1];
    #pragma unroll
    for (int o = 16; o; o >>= 1) {
        #pragma unroll
        for (int r = 0; r < 4; ++r)
            p[r] += __shfl_xor_sync(0xffffffffu, p[r], o);
    }
    float z2h[4];
    #pragma unroll
    for (int r = 0; r < 4; ++r) z2h[r] = 0.5f * p[r];

    // g-dot for 4 rows: mu loaded ONCE, 16 accumulators
    float gv[4];
    {
        const int k = l & 15, h = l >> 4;
        const float4* mr = (const float4*)&mu_t[k][h * 32];
        const float4* zr0 = (const float4*)&z_s[4 * w + 0][h * 32];
        const float4* zr1 = (const float4*)&z_s[4 * w + 1][h * 32];
        const float4* zr2 = (const float4*)&z_s[4 * w + 2][h * 32];
        const float4* zr3 = (const float4*)&z_s[4 * w + 3][h * 32];
        float a[4][4];
        #pragma unroll
        for (int r = 0; r < 4; ++r)
            #pragma unroll
            for (int x = 0; x < 4; ++x) a[r][x] = 0.f;
        #pragma unroll
        for (int j = 0; j < 8; ++j) {
            const float4 mv = mr[j];
            const float4 q0 = zr0[j], q1 = zr1[j], q2 = zr2[j], q3 = zr3[j];
            a[0][0] = fmaf(q0.x, mv.x, a[0][0]); a[0][1] = fmaf(q0.y, mv.y, a[0][1]);
            a[0][2] = fmaf(q0.z, mv.z, a[0][2]); a[0][3] = fmaf(q0.w, mv.w, a[0][3]);
            a[1][0] = fmaf(q1.x, mv.x, a[1][0]); a[1][1] = fmaf(q1.y, mv.y, a[1][1]);
            a[1][2] = fmaf(q1.z, mv.z, a[1][2]); a[1][3] = fmaf(q1.w, mv.w, a[1][3]);
            a[2][0] = fmaf(q2.x, mv.x, a[2][0]); a[2][1] = fmaf(q2.y, mv.y, a[2][1]);
            a[2][2] = fmaf(q2.z, mv.z, a[2][2]); a[2][3] = fmaf(q2.w, mv.w, a[2][3]);
            a[3][0] = fmaf(q3.x, mv.x, a[3][0]); a[3][1] = fmaf(q3.y, mv.y, a[3][1]);
            a[3][2] = fmaf(q3.z, mv.z, a[3][2]); a[3][3] = fmaf(q3.w, mv.w, a[3][3]);
        }
        #pragma unroll
        for (int r = 0; r < 4; ++r) {
            float acc = (a[r][0] + a[r][1]) + (a[r][2] + a[r][3]);
            acc += __shfl_xor_sync(0xffffffffu, acc, 16);
            gv[r] = acc;         // lanes l and l+16 hold g_{l&15} for row r
        }
    }

    // ---- uniform hot loop: 5 categories x 4 rows = 20 independent chains ----
    float qv[5][4], Dv[5][4];
    #pragma unroll
    for (int i = 0; i < 5; ++i) {
        const float4 q4 = c4r[i];                   // k1, 0.5*mB2, recip, s
        const float2 b2 = cbr[i];
        const int ab = __float_as_int(b2.y);
        const int Ai = ab & 15, Bi = (ab >> 8) & 15;
        #pragma unroll
        for (int r = 0; r < 4; ++r) {
            const float gA = __shfl_sync(0xffffffffu, gv[r], Ai);
            const float gB = __shfl_sync(0xffffffffu, gv[r], Bi);
            const float hbsq  = (z2h[r] - gB) + q4.y;
            const float delta = (q4.x - gB) + gA;
            const float nu    = delta * q4.z;
            qv[i][r] = fmaf(0.5f * delta, nu, -hbsq) + b2.x;
            const float ns   = nu * q4.w;
            const float eta1 = q4.w - ns;
            const float eta2 = -ns;
            const float u1 = eta1 * fmaf(PHI_C3, eta1 * eta1, PHI_C1);
            const float u2 = eta2 * fmaf(PHI_C3, eta2 * eta2, PHI_C1);
            Dv[i][r] = fmaxf(tanh_approx(u1) - tanh_approx(u2), 2e-16f);
        }
    }

    float m[4];
    #pragma unroll
    for (int r = 0; r < 4; ++r) {
        m[r] = qv[0][r];
        #pragma unroll
        for (int i = 1; i < 5; ++i) m[r] = fmaxf(m[r], qv[i][r]);
    }
    #pragma unroll
    for (int o = 16; o; o >>= 1) {
        #pragma unroll
        for (int r = 0; r < 4; ++r)
            m[r] = fmaxf(m[r], __shfl_xor_sync(0xffffffffu, m[r], o));
    }

    float ss[4] = {0.f, 0.f, 0.f, 0.f};
    #pragma unroll
    for (int i = 0; i < 5; ++i)
        #pragma unroll
        for (int r = 0; r < 4; ++r)
            ss[r] = fmaf(__expf(qv[i][r] - m[r]), Dv[i][r], ss[r]);

    #pragma unroll
    for (int o = 16; o; o >>= 1) {
        #pragma unroll
        for (int r = 0; r < 4; ++r)
            ss[r] += __shfl_xor_sync(0xffffffffu, ss[r], o);
    }

    if (l == 0) {
        #pragma unroll
        for (int r = 0; r < 4; ++r)
            rowres[4 * w + r] = m[r] + __logf(ss[r]);
    }
    __syncthreads();

    // ---- per-block partial + last-block-done finalize ----
    if (t == 0) {
        float s = 0.f;
        #pragma unroll
        for (int r = 0; r < ROWS_PER_BLK; ++r) s += rowres[r];
        d_partials[blockIdx.x] = s;
        __threadfence();
        const unsigned int ticket = atomicAdd(&d_counter, 1u);
        s_is_last = (ticket == (unsigned)(gridDim.x - 1));
    }
    __syncthreads();

    if (s_is_last) {
        volatile float* vp = d_partials;
        float s = 0.f;
        for (int i = t; i < MAIN_BLOCKS; i += NTHR) s += vp[i];
        red[t] = s; __syncthreads();
        for (int o = NTHR / 2; o; o >>= 1) { if (t < o) red[t] += red[t + o]; __syncthreads(); }
        if (t == 0) {
            out[0] = red[0] * (1.0f / (float)NROWS);
            d_counter = 0;                 // reset for next graph replay
        }
    }
}

// ---------------------------------------------------------------------------
extern "C" void kernel_launch(void* const* d_in, const int* in_sizes, int n_in,
                              void* d_out, int out_size)
{
    (void)in_sizes; (void)n_in; (void)out_size;
    const float* z  = (const float*)d_in[0];
    const float* pi = (const float*)d_in[1];
    const float* mu = (const float*)d_in[2];
    float* out = (float*)d_out;

    fused_kernel<<<MAIN_BLOCKS, NTHR>>>(z, pi, mu, out);
}

// round 12
// speedup vs baseline: 1.0903x; 1.0903x over previous
#include <cuda_runtime.h>
#include <math.h>

// Problem constants (fixed by the reference)
#define N_K        16
#define C_CAT      136          // 16*17/2 upper-tri pairs
#define C_PAD      160          // padded to 32*5 for a uniform unrolled loop
#define DIM        64
#define MU_PITCH   68           // DIM + 4 pad: rows 16B-aligned
#define NROWS      8192         // 512 * 16
#define ROWS_PER_BLK 16         // 8 warps x 2 rows
#define NTHR       256
#define MAIN_BLOCKS (NROWS / ROWS_PER_BLK)   // 512

#define LOG2PI_F   1.8378770664093453f
#define LN2_F      0.6931471805599453f
#define L2E_F      1.4426950408889634f
// Phi-tanh approx: Phi(x) ~= 0.5*(1+tanh(C1*x + C3*x^3))
#define PHI_C1     0.7978845608028654f
#define PHI_C3     0.03567740813712f

// ---- device scratch (static globals; no allocation) ----
__device__ float  d_partials[MAIN_BLOCKS];
__device__ unsigned int d_counter = 0;

typedef unsigned long long ull;

__device__ __forceinline__ float tanh_approx(float x) {
    float r; asm("tanh.approx.f32 %0, %1;" : "=f"(r) : "f"(x)); return r;
}
__device__ __forceinline__ float ex2_approx(float x) {
    float r; asm("ex2.approx.f32 %0, %1;" : "=f"(r) : "f"(x)); return r;
}
// f32x2 packed helpers (sm_103a)
__device__ __forceinline__ ull pk2(float a, float b) {
    ull r; asm("mov.b64 %0, {%1,%2};" : "=l"(r)
               : "r"(__float_as_uint(a)), "r"(__float_as_uint(b))); return r;
}
__device__ __forceinline__ ull dup2(float a) { return pk2(a, a); }
__device__ __forceinline__ void upk2(ull v, float& a, float& b) {
    unsigned int x, y; asm("mov.b64 {%0,%1}, %2;" : "=r"(x), "=r"(y) : "l"(v));
    a = __uint_as_float(x); b = __uint_as_float(y);
}
__device__ __forceinline__ ull add2(ull a, ull b) {
    ull r; asm("add.rn.f32x2 %0, %1, %2;" : "=l"(r) : "l"(a), "l"(b)); return r;
}
__device__ __forceinline__ ull mul2(ull a, ull b) {
    ull r; asm("mul.rn.f32x2 %0, %1, %2;" : "=l"(r) : "l"(a), "l"(b)); return r;
}
__device__ __forceinline__ ull fma2p(ull a, ull b, ull c) {
    ull r; asm("fma.rn.f32x2 %0, %1, %2, %3;" : "=l"(r) : "l"(a), "l"(b), "l"(c)); return r;
}

// ---------------------------------------------------------------------------
// SINGLE fused kernel. 16 rows/block (256 thr), two rows per warp.
// Prologue: warp-local softmax; Gram matrix in smem (1 dot/thread, closed-form
// pair decode); per-category constants from Gram.  Hot loop: f32x2-packed
// 2-row math, global-shift LSE (q <= base <= M*, no per-row max needed).
// Diagonal pairs encoded as heavy categories (k1=0, recip=0 -> nu=0; s=20 ->
// tanh(u1)=1, tanh(u2)=0 -> D=1; base=lp). Slots [136,160): base=-1e30.
// ---------------------------------------------------------------------------
__global__ __launch_bounds__(NTHR) void fused_kernel(const float* __restrict__ z,
                                                     const float* __restrict__ pi,
                                                     const float* __restrict__ mu,
                                                     float* __restrict__ out)
{
    __shared__ float  mu_t[N_K][MU_PITCH];          // transposed mu
    __shared__ float  z_s [ROWS_PER_BLK][DIM];      // 4 KB
    __shared__ float  g_gram[N_K][N_K + 1];         // Gram(mu_k, mu_j)
    __shared__ float4 c4_s[C_PAD];                  // {k1, 0.5*mB2, recip, s}
    __shared__ float2 cb_s[C_PAD];                  // {base, bitcast(A|B<<8)}
    __shared__ float  rowres[ROWS_PER_BLK];
    __shared__ float  red[NTHR];
    __shared__ int    s_is_last;

    const int t = threadIdx.x;
    const int w = t >> 5;        // warp; handles rows 2w, 2w+1
    const int l = t & 31;

    // prefetch both rows' z into registers immediately
    const int row0 = blockIdx.x * ROWS_PER_BLK;
    const float* zp0 = z + (row0 + 2 * w) * DIM;
    const float za0 = zp0[l], za1 = zp0[l + 32];
    const float zb0 = zp0[DIM + l], zb1 = zp0[DIM + l + 32];

    // stage mu transposed
    for (int i = t; i < DIM * N_K; i += NTHR) {
        const int d = i >> 4, k = i & 15;           // mu is [d][k]
        mu_t[k][d] = mu[i];
    }
    // stage this warp's z rows
    z_s[2 * w][l]          = za0;
    z_s[2 * w][l + 32]     = za1;
    z_s[2 * w + 1][l]      = zb0;
    z_s[2 * w + 1][l + 32] = zb1;
    // padding category slots
    if (t >= C_CAT && t < C_PAD) {
        c4_s[t] = make_float4(0.f, 0.f, 0.f, 20.f);
        cb_s[t] = make_float2(-1e30f, __int_as_float(0));
    }

    // warp-local softmax denominator over the 136 pi logits
    const float v0 = pi[l], v1 = pi[l + 32], v2 = pi[l + 64], v3 = pi[l + 96];
    const float v4 = (l < 8) ? pi[128 + l] : -INFINITY;
    float mx = fmaxf(fmaxf(fmaxf(v0, v1), fmaxf(v2, v3)), v4);
    #pragma unroll
    for (int o = 16; o; o >>= 1) mx = fmaxf(mx, __shfl_xor_sync(0xffffffffu, mx, o));
    float sm = __expf(v0 - mx) + __expf(v1 - mx) + __expf(v2 - mx) + __expf(v3 - mx)
             + ((l < 8) ? __expf(v4 - mx) : 0.f);
    #pragma unroll
    for (int o = 16; o; o >>= 1) sm += __shfl_xor_sync(0xffffffffu, sm, o);
    const float lgden = mx + __logf(sm);

    __syncthreads();                                 // mu_t ready

    // ---- Gram pass: thread c (<136) computes dot(mu_A, mu_B) ----
    int Ad = 0, Bd = 0;
    if (t < C_CAT) {
        const float cf = (float)t;
        Ad = (int)floorf((33.0f - sqrtf(fmaf(-8.0f, cf, 1089.0f))) * 0.5f);
        Bd = t - ((33 - Ad) * Ad >> 1) + Ad;         // f(A) = A*(33-A)/2

        const float4* ma = (const float4*)&mu_t[Ad][0];
        const float4* mb = (const float4*)&mu_t[Bd][0];
        float a0 = 0.f, a1 = 0.f, a2 = 0.f, a3 = 0.f;
        #pragma unroll
        for (int j = 0; j < 16; ++j) {
            const float4 fa = ma[j];
            const float4 fb = mb[j];
            a0 = fmaf(fa.x, fb.x, a0); a1 = fmaf(fa.y, fb.y, a1);
            a2 = fmaf(fa.z, fb.z, a2); a3 = fmaf(fa.w, fb.w, a3);
        }
        const float g = (a0 + a1) + (a2 + a3);
        g_gram[Ad][Bd] = g;
        g_gram[Bd][Ad] = g;
    }
    __syncthreads();                                 // Gram ready

    // ---- per-category constants from Gram ----
    if (t < C_CAT) {
        const float GAA = g_gram[Ad][Ad];
        const float GAB = g_gram[Ad][Bd];
        const float GBB = g_gram[Bd][Bd];
        const float invsig = (GAA - 2.0f * GAB) + GBB;
        const float lp = -32.0f * LOG2PI_F + (__ldg(&pi[t]) - lgden);

        float base, recip, s, k1;
        if (Ad == Bd) {                      // diag: inv_sig == 0 exactly
            base = lp; recip = 0.f; s = 20.f; k1 = 0.f;
        } else {
            const float clip_is = fminf(fmaxf(invsig, 1e-12f), 1e30f);
            s     = sqrtf(clip_is);
            base  = lp + 0.5f * (LOG2PI_F - __logf(clip_is)) - LN2_F;
            recip = 1.0f / invsig;
            k1    = GBB - GAB;               // dot(alpha, mu_B)
        }
        c4_s[t] = make_float4(k1, 0.5f * GBB, recip, s);
        cb_s[t] = make_float2(base, __int_as_float(Ad | (Bd << 8)));
    }
    __syncthreads();                                 // constants ready

    // ---- M* = max_c base (per-block uniform; q <= base always) ----
    float bmax = cb_s[l].x;
    #pragma unroll
    for (int i = 1; i < 5; ++i) bmax = fmaxf(bmax, cb_s[l + 32 * i].x);
    #pragma unroll
    for (int o = 16; o; o >>= 1) bmax = fmaxf(bmax, __shfl_xor_sync(0xffffffffu, bmax, o));
    const float Mstar = bmax;

    // 0.5*|z|^2, both rows through one butterfly
    float p0 = za0 * za0 + za1 * za1;
    float p1 = zb0 * zb0 + zb1 * zb1;
    #pragma unroll
    for (int o = 16; o; o >>= 1) {
        p0 += __shfl_xor_sync(0xffffffffu, p0, o);
        p1 += __shfl_xor_sync(0xffffffffu, p1, o);
    }

    // g-dot for both rows: mu loaded once
    float gv0, gv1;
    {
        const int k = l & 15, h = l >> 4;
        const float4* mr  = (const float4*)&mu_t[k][h * 32];
        const float4* zr0 = (const float4*)&z_s[2 * w][h * 32];
        const float4* zr1 = (const float4*)&z_s[2 * w + 1][h * 32];
        float a0 = 0.f, a1 = 0.f, a2 = 0.f, a3 = 0.f;
        float b0 = 0.f, b1 = 0.f, b2 = 0.f, b3 = 0.f;
        #pragma unroll
        for (int j = 0; j < 8; ++j) {
            const float4 mv  = mr[j];
            const float4 q0 = zr0[j];
            const float4 q1 = zr1[j];
            a0 = fmaf(q0.x, mv.x, a0); a1 = fmaf(q0.y, mv.y, a1);
            a2 = fmaf(q0.z, mv.z, a2); a3 = fmaf(q0.w, mv.w, a3);
            b0 = fmaf(q1.x, mv.x, b0); b1 = fmaf(q1.y, mv.y, b1);
            b2 = fmaf(q1.z, mv.z, b2); b3 = fmaf(q1.w, mv.w, b3);
        }
        float acc0 = (a0 + a1) + (a2 + a3);
        float acc1 = (b0 + b1) + (b2 + b3);
        acc0 += __shfl_xor_sync(0xffffffffu, acc0, 16);
        acc1 += __shfl_xor_sync(0xffffffffu, acc1, 16);
        gv0 = acc0;              // lanes l, l+16 hold g_{l&15} (row 2w)
        gv1 = acc1;              // (row 2w+1)
    }

    // packed loop-invariants
    const ull NEG1  = dup2(-1.0f);
    const ull HALF2 = dup2(0.5f);
    const ull C1_2  = dup2(PHI_C1);
    const ull C3_2  = dup2(PHI_C3);
    const ull L2E2  = dup2(L2E_F);
    const ull nM2   = dup2(-Mstar);
    const ull z2h2  = pk2(0.5f * p0, 0.5f * p1);

    // ---- hot loop: 5 categories, both rows packed in f32x2 ----
    float ss0 = 0.f, ss1 = 0.f;
    #pragma unroll
    for (int i = 0; i < 5; ++i) {
        const int c = l + 32 * i;
        const float4 q4 = c4_s[c];                  // k1, 0.5*mB2, recip, s
        const float2 b2 = cb_s[c];
        const int ab = __float_as_int(b2.y);
        const int Ai = ab & 15, Bi = (ab >> 8) & 15;
        const float gA0 = __shfl_sync(0xffffffffu, gv0, Ai);
        const float gB0 = __shfl_sync(0xffffffffu, gv0, Bi);
        const float gA1 = __shfl_sync(0xffffffffu, gv1, Ai);
        const float gB1 = __shfl_sync(0xffffffffu, gv1, Bi);

        const ull gA2  = pk2(gA0, gA1);
        const ull gB2  = pk2(gB0, gB1);
        const ull ngB2 = mul2(gB2, NEG1);
        const ull k1_2 = dup2(q4.x);
        const ull mBh2 = dup2(q4.y);
        const ull rc2  = dup2(q4.z);
        const ull s2   = dup2(q4.w);
        const ull bs2  = dup2(b2.x);

        const ull hb2 = add2(add2(z2h2, ngB2), mBh2);       // 0.5*beta_sq
        const ull de2 = add2(add2(k1_2, ngB2), gA2);        // delta
        const ull nu2 = mul2(de2, rc2);
        const ull q2  = add2(fma2p(mul2(de2, HALF2), nu2, mul2(hb2, NEG1)), bs2);

        const ull ns2  = mul2(nu2, s2);
        const ull nns2 = mul2(ns2, NEG1);                   // eta2 = -nu*s
        const ull e1_2 = add2(s2, nns2);                    // eta1 = (1-nu)*s
        const ull u1_2 = mul2(e1_2, fma2p(C3_2, mul2(e1_2, e1_2), C1_2));
        const ull u2_2 = mul2(nns2, fma2p(C3_2, mul2(nns2, nns2), C1_2));

        float u1a, u1b, u2a, u2b;
        upk2(u1_2, u1a, u1b);
        upk2(u2_2, u2a, u2b);
        const float D0 = fmaxf(tanh_approx(u1a) - tanh_approx(u2a), 2e-16f);
        const float D1 = fmaxf(tanh_approx(u1b) - tanh_approx(u2b), 2e-16f);

        const ull ed2 = mul2(add2(q2, nM2), L2E2);          // (q-M*)*log2e
        float x0, x1;
        upk2(ed2, x0, x1);
        ss0 = fmaf(ex2_approx(x0), D0, ss0);
        ss1 = fmaf(ex2_approx(x1), D1, ss1);
    }

    // warp sum of ss (both rows)
    #pragma unroll
    for (int o = 16; o; o >>= 1) {
        ss0 += __shfl_xor_sync(0xffffffffu, ss0, o);
        ss1 += __shfl_xor_sync(0xffffffffu, ss1, o);
    }

    if (l == 0) {
        rowres[2 * w]     = Mstar + __logf(fmaxf(ss0, 1e-37f));
        rowres[2 * w + 1] = Mstar + __logf(fmaxf(ss1, 1e-37f));
    }
    __syncthreads();

    // ---- per-block partial + last-block-done finalize ----
    if (t == 0) {
        float s = 0.f;
        #pragma unroll
        for (int r = 0; r < ROWS_PER_BLK; ++r) s += rowres[r];
        d_partials[blockIdx.x] = s;
        __threadfence();
        const unsigned int ticket = atomicAdd(&d_counter, 1u);
        s_is_last = (ticket == (unsigned)(gridDim.x - 1));
    }
    __syncthreads();

    if (s_is_last) {
        volatile float* vp = d_partials;
        float s = 0.f;
        for (int i = t; i < MAIN_BLOCKS; i += NTHR) s += vp[i];
        red[t] = s; __syncthreads();
        for (int o = NTHR / 2; o; o >>= 1) { if (t < o) red[t] += red[t + o]; __syncthreads(); }
        if (t == 0) {
            out[0] = red[0] * (1.0f / (float)NROWS);
            d_counter = 0;                 // reset for next graph replay
        }
    }
}

// ---------------------------------------------------------------------------
extern "C" void kernel_launch(void* const* d_in, const int* in_sizes, int n_in,
                              void* d_out, int out_size)
{
    (void)in_sizes; (void)n_in; (void)out_size;
    const float* z  = (const float*)d_in[0];
    const float* pi = (const float*)d_in[1];
    const float* mu = (const float*)d_in[2];
    float* out = (float*)d_out;

    fused_kernel<<<MAIN_BLOCKS, NTHR>>>(z, pi, mu, out);
}

// round 13
// speedup vs baseline: 1.1544x; 1.0588x over previous
#include <cuda_runtime.h>
#include <math.h>

// Problem constants (fixed by the reference)
#define N_K        16
#define C_CAT      136          // 16*17/2 upper-tri pairs
#define C_PAD      160          // padded to 32*5 for a uniform unrolled loop
#define DIM        64
#define MU_PITCH   68           // DIM + 4 pad: rows 16B-aligned
#define NROWS      8192         // 512 * 16
#define ROWS_PER_BLK 16         // 8 warps x 2 rows
#define NTHR       256
#define MAIN_BLOCKS (NROWS / ROWS_PER_BLK)   // 512

#define LOG2PI_F   1.8378770664093453f
#define LN2_F      0.6931471805599453f
#define L2E_F      1.4426950408889634f
// Phi-tanh approx: Phi(x) ~= 0.5*(1+tanh(C1*x + C3*x^3))
#define PHI_C1     0.7978845608028654f
#define PHI_C3     0.03567740813712f

// ---- device scratch (static globals; no allocation) ----
__device__ float  d_partials[MAIN_BLOCKS];
__device__ unsigned int d_counter = 0;

typedef unsigned long long ull;

__device__ __forceinline__ float tanh_approx(float x) {
    float r; asm("tanh.approx.f32 %0, %1;" : "=f"(r) : "f"(x)); return r;
}
__device__ __forceinline__ float ex2_approx(float x) {
    float r; asm("ex2.approx.f32 %0, %1;" : "=f"(r) : "f"(x)); return r;
}
// f32x2 packed helpers (sm_103a)
__device__ __forceinline__ ull pk2(float a, float b) {
    ull r; asm("mov.b64 %0, {%1,%2};" : "=l"(r)
               : "r"(__float_as_uint(a)), "r"(__float_as_uint(b))); return r;
}
__device__ __forceinline__ ull dup2(float a) { return pk2(a, a); }
__device__ __forceinline__ void upk2(ull v, float& a, float& b) {
    unsigned int x, y; asm("mov.b64 {%0,%1}, %2;" : "=r"(x), "=r"(y) : "l"(v));
    a = __uint_as_float(x); b = __uint_as_float(y);
}
__device__ __forceinline__ ull add2(ull a, ull b) {
    ull r; asm("add.rn.f32x2 %0, %1, %2;" : "=l"(r) : "l"(a), "l"(b)); return r;
}
__device__ __forceinline__ ull mul2(ull a, ull b) {
    ull r; asm("mul.rn.f32x2 %0, %1, %2;" : "=l"(r) : "l"(a), "l"(b)); return r;
}
__device__ __forceinline__ ull fma2p(ull a, ull b, ull c) {
    ull r; asm("fma.rn.f32x2 %0, %1, %2, %3;" : "=l"(r) : "l"(a), "l"(b), "l"(c)); return r;
}

// ---------------------------------------------------------------------------
// SINGLE fused kernel. 16 rows/block (256 thr), two rows per warp.
// log2-domain hot loop: x = baseC2 + gBL + 0.5*deltaL*nu - shiftL,
// shiftL = bC2max + z2h*log2e (per-row packed const; z2h cancels in rowres).
// Table: c4 = {k1L, recipX=recip/log2e, s, baseC2=(base-mB2/2)*log2e}, ab int.
// Diagonal pairs: k1L=0, recipX=0 -> nu=0; s=20 -> D=1; baseC2=(lp-GBB/2)L2E.
// Slots [136,160): baseC2=-1e30 (ex2 -> 0).
// ---------------------------------------------------------------------------
__global__ __launch_bounds__(NTHR) void fused_kernel(const float* __restrict__ z,
                                                     const float* __restrict__ pi,
                                                     const float* __restrict__ mu,
                                                     float* __restrict__ out)
{
    __shared__ float  mu_t[N_K][MU_PITCH];          // transposed mu
    __shared__ float  z_s [ROWS_PER_BLK][DIM];      // 4 KB
    __shared__ float  g_gram[N_K][N_K + 1];         // Gram(mu_k, mu_j)
    __shared__ float4 c4_s[C_PAD];                  // {k1L, recipX, s, baseC2}
    __shared__ int    ab_s[C_PAD];                  // A | B<<8
    __shared__ float  rowres[ROWS_PER_BLK];
    __shared__ float  red[NTHR];
    __shared__ int    s_is_last;

    const int t = threadIdx.x;
    const int w = t >> 5;        // warp; handles rows 2w, 2w+1
    const int l = t & 31;

    // prefetch both rows' z into registers immediately
    const int row0 = blockIdx.x * ROWS_PER_BLK;
    const float* zp0 = z + (row0 + 2 * w) * DIM;
    const float za0 = zp0[l], za1 = zp0[l + 32];
    const float zb0 = zp0[DIM + l], zb1 = zp0[DIM + l + 32];

    // stage mu transposed
    for (int i = t; i < DIM * N_K; i += NTHR) {
        const int d = i >> 4, k = i & 15;           // mu is [d][k]
        mu_t[k][d] = mu[i];
    }
    // stage this warp's z rows
    z_s[2 * w][l]          = za0;
    z_s[2 * w][l + 32]     = za1;
    z_s[2 * w + 1][l]      = zb0;
    z_s[2 * w + 1][l + 32] = zb1;
    // padding category slots
    if (t >= C_CAT && t < C_PAD) {
        c4_s[t] = make_float4(0.f, 0.f, 20.f, -1e30f);
        ab_s[t] = 0;
    }

    // warp-local softmax denominator over the 136 pi logits
    const float v0 = pi[l], v1 = pi[l + 32], v2 = pi[l + 64], v3 = pi[l + 96];
    const float v4 = (l < 8) ? pi[128 + l] : -INFINITY;
    float mx = fmaxf(fmaxf(fmaxf(v0, v1), fmaxf(v2, v3)), v4);
    #pragma unroll
    for (int o = 16; o; o >>= 1) mx = fmaxf(mx, __shfl_xor_sync(0xffffffffu, mx, o));
    float sm = __expf(v0 - mx) + __expf(v1 - mx) + __expf(v2 - mx) + __expf(v3 - mx)
             + ((l < 8) ? __expf(v4 - mx) : 0.f);
    #pragma unroll
    for (int o = 16; o; o >>= 1) sm += __shfl_xor_sync(0xffffffffu, sm, o);
    const float lgden = mx + __logf(sm);

    __syncthreads();                                 // mu_t ready

    // ---- Gram pass: thread c (<136) computes dot(mu_A, mu_B) ----
    int Ad = 0, Bd = 0;
    if (t < C_CAT) {
        const float cf = (float)t;
        Ad = (int)floorf((33.0f - sqrtf(fmaf(-8.0f, cf, 1089.0f))) * 0.5f);
        Bd = t - ((33 - Ad) * Ad >> 1) + Ad;         // f(A) = A*(33-A)/2

        const float4* ma = (const float4*)&mu_t[Ad][0];
        const float4* mb = (const float4*)&mu_t[Bd][0];
        float a0 = 0.f, a1 = 0.f, a2 = 0.f, a3 = 0.f;
        #pragma unroll
        for (int j = 0; j < 16; ++j) {
            const float4 fa = ma[j];
            const float4 fb = mb[j];
            a0 = fmaf(fa.x, fb.x, a0); a1 = fmaf(fa.y, fb.y, a1);
            a2 = fmaf(fa.z, fb.z, a2); a3 = fmaf(fa.w, fb.w, a3);
        }
        const float g = (a0 + a1) + (a2 + a3);
        g_gram[Ad][Bd] = g;
        g_gram[Bd][Ad] = g;
    }
    __syncthreads();                                 // Gram ready

    // ---- per-category constants from Gram (log2 domain) ----
    if (t < C_CAT) {
        const float GAA = g_gram[Ad][Ad];
        const float GAB = g_gram[Ad][Bd];
        const float GBB = g_gram[Bd][Bd];
        const float invsig = (GAA - 2.0f * GAB) + GBB;
        const float lp = -32.0f * LOG2PI_F + (__ldg(&pi[t]) - lgden);

        float baseC, recipX, s, k1L;
        if (Ad == Bd) {                      // diag: inv_sig == 0 exactly
            baseC = lp - 0.5f * GBB; recipX = 0.f; s = 20.f; k1L = 0.f;
        } else {
            const float clip_is = fminf(fmaxf(invsig, 1e-12f), 1e30f);
            s      = sqrtf(clip_is);
            baseC  = lp + 0.5f * (LOG2PI_F - __logf(clip_is)) - LN2_F - 0.5f * GBB;
            recipX = (1.0f / invsig) * (1.0f / L2E_F);
            k1L    = (GBB - GAB) * L2E_F;    // dot(alpha, mu_B) * log2e
        }
        c4_s[t] = make_float4(k1L, recipX, s, baseC * L2E_F);
        ab_s[t] = Ad | (Bd << 8);
    }
    __syncthreads();                                 // constants ready

    // ---- bC2max = max_c baseC2 (per-block uniform shift component) ----
    float bmax = c4_s[l].w;
    #pragma unroll
    for (int i = 1; i < 5; ++i) bmax = fmaxf(bmax, c4_s[l + 32 * i].w);
    #pragma unroll
    for (int o = 16; o; o >>= 1) bmax = fmaxf(bmax, __shfl_xor_sync(0xffffffffu, bmax, o));
    const float bC2max = bmax;

    // 0.5*|z|^2, both rows through one butterfly
    float p0 = za0 * za0 + za1 * za1;
    float p1 = zb0 * zb0 + zb1 * zb1;
    #pragma unroll
    for (int o = 16; o; o >>= 1) {
        p0 += __shfl_xor_sync(0xffffffffu, p0, o);
        p1 += __shfl_xor_sync(0xffffffffu, p1, o);
    }

    // g-dot for both rows: mu loaded once; results prescaled by log2e
    float gvL0, gvL1;
    {
        const int k = l & 15, h = l >> 4;
        const float4* mr  = (const float4*)&mu_t[k][h * 32];
        const float4* zr0 = (const float4*)&z_s[2 * w][h * 32];
        const float4* zr1 = (const float4*)&z_s[2 * w + 1][h * 32];
        float a0 = 0.f, a1 = 0.f, a2 = 0.f, a3 = 0.f;
        float b0 = 0.f, b1 = 0.f, b2 = 0.f, b3 = 0.f;
        #pragma unroll
        for (int j = 0; j < 8; ++j) {
            const float4 mv = mr[j];
            const float4 q0 = zr0[j];
            const float4 q1 = zr1[j];
            a0 = fmaf(q0.x, mv.x, a0); a1 = fmaf(q0.y, mv.y, a1);
            a2 = fmaf(q0.z, mv.z, a2); a3 = fmaf(q0.w, mv.w, a3);
            b0 = fmaf(q1.x, mv.x, b0); b1 = fmaf(q1.y, mv.y, b1);
            b2 = fmaf(q1.z, mv.z, b2); b3 = fmaf(q1.w, mv.w, b3);
        }
        float acc0 = (a0 + a1) + (a2 + a3);
        float acc1 = (b0 + b1) + (b2 + b3);
        acc0 += __shfl_xor_sync(0xffffffffu, acc0, 16);
        acc1 += __shfl_xor_sync(0xffffffffu, acc1, 16);
        gvL0 = acc0 * L2E_F;     // lanes l, l+16 hold g_{l&15}*log2e (row 2w)
        gvL1 = acc1 * L2E_F;     // (row 2w+1)
    }

    // packed loop-invariants
    const ull NEG1  = dup2(-1.0f);
    const ull HALF2 = dup2(0.5f);
    const ull C1_2  = dup2(PHI_C1);
    const ull C3_2  = dup2(PHI_C3);
    // per-row shift: shiftL_r = bC2max + z2h_r*log2e (z2h cancels in rowres)
    const ull nSh2  = pk2(-fmaf(0.5f * p0, L2E_F, bC2max),
                          -fmaf(0.5f * p1, L2E_F, bC2max));

    // ---- hot loop: 5 categories, both rows packed in f32x2 ----
    float ss0 = 0.f, ss1 = 0.f;
    #pragma unroll
    for (int i = 0; i < 5; ++i) {
        const int c = l + 32 * i;
        const float4 q4 = c4_s[c];                  // k1L, recipX, s, baseC2
        const int ab = ab_s[c];
        const int Ai = ab & 15, Bi = (ab >> 8) & 15;
        const float gA0 = __shfl_sync(0xffffffffu, gvL0, Ai);
        const float gB0 = __shfl_sync(0xffffffffu, gvL0, Bi);
        const float gA1 = __shfl_sync(0xffffffffu, gvL1, Ai);
        const float gB1 = __shfl_sync(0xffffffffu, gvL1, Bi);

        const ull gA2 = pk2(gA0, gA1);
        const ull gB2 = pk2(gB0, gB1);
        const ull k1_2 = dup2(q4.x);
        const ull rc2  = dup2(q4.y);
        const ull s2   = dup2(q4.z);
        const ull bc2  = dup2(q4.w);

        const ull deL = add2(fma2p(gB2, NEG1, k1_2), gA2);  // deltaL = delta*log2e
        const ull nu2 = mul2(deL, rc2);                     // true nu
        const ull bg  = add2(add2(bc2, gB2), nSh2);         // baseC2 + gBL - shift
        const ull xs  = fma2p(mul2(deL, HALF2), nu2, bg);   // exponent (log2)

        const ull ns2  = mul2(nu2, s2);
        const ull nns2 = mul2(ns2, NEG1);                   // eta2 = -nu*s
        const ull e1_2 = add2(s2, nns2);                    // eta1 = (1-nu)*s
        const ull u1_2 = mul2(e1_2, fma2p(C3_2, mul2(e1_2, e1_2), C1_2));
        const ull u2_2 = mul2(nns2, fma2p(C3_2, mul2(nns2, nns2), C1_2));

        float u1a, u1b, u2a, u2b, x0, x1;
        upk2(u1_2, u1a, u1b);
        upk2(u2_2, u2a, u2b);
        upk2(xs, x0, x1);
        const float D0 = fmaxf(tanh_approx(u1a) - tanh_approx(u2a), 2e-16f);
        const float D1 = fmaxf(tanh_approx(u1b) - tanh_approx(u2b), 2e-16f);
        ss0 = fmaf(ex2_approx(x0), D0, ss0);
        ss1 = fmaf(ex2_approx(x1), D1, ss1);
    }

    // warp sum of ss (both rows)
    #pragma unroll
    for (int o = 16; o; o >>= 1) {
        ss0 += __shfl_xor_sync(0xffffffffu, ss0, o);
        ss1 += __shfl_xor_sync(0xffffffffu, ss1, o);
    }

    // rowres = bC2max*ln2 + log(ss)   (z2h cancels exactly)
    if (l == 0) {
        const float bnat = bC2max * LN2_F;
        rowres[2 * w]     = bnat + __logf(fmaxf(ss0, 1e-37f));
        rowres[2 * w + 1] = bnat + __logf(fmaxf(ss1, 1e-37f));
    }
    __syncthreads();

    // ---- per-block partial + last-block-done finalize ----
    if (t == 0) {
        float s = 0.f;
        #pragma unroll
        for (int r = 0; r < ROWS_PER_BLK; ++r) s += rowres[r];
        d_partials[blockIdx.x] = s;
        __threadfence();
        const unsigned int ticket = atomicAdd(&d_counter, 1u);
        s_is_last = (ticket == (unsigned)(gridDim.x - 1));
    }
    __syncthreads();

    if (s_is_last) {
        // partials are visible (all writers fenced before the final ticket)
        float s = 0.f;
        if (t < MAIN_BLOCKS / 4) {
            const float4 v = __ldcg(((const float4*)d_partials) + t);
            s = (v.x + v.y) + (v.z + v.w);
        }
        red[t] = s; __syncthreads();
        for (int o = NTHR / 2; o; o >>= 1) { if (t < o) red[t] += red[t + o]; __syncthreads(); }
        if (t == 0) {
            out[0] = red[0] * (1.0f / (float)NROWS);
            d_counter = 0;                 // reset for next graph replay
        }
    }
}

// ---------------------------------------------------------------------------
extern "C" void kernel_launch(void* const* d_in, const int* in_sizes, int n_in,
                              void* d_out, int out_size)
{
    (void)in_sizes; (void)n_in; (void)out_size;
    const float* z  = (const float*)d_in[0];
    const float* pi = (const float*)d_in[1];
    const float* mu = (const float*)d_in[2];
    float* out = (float*)d_out;

    fused_kernel<<<MAIN_BLOCKS, NTHR>>>(z, pi, mu, out);
}

// round 14
// speedup vs baseline: 1.1805x; 1.0226x over previous
#include <cuda_runtime.h>
#include <math.h>

// Problem constants (fixed by the reference)
#define N_K        16
#define C_CAT      136          // 16*17/2 upper-tri pairs
#define C_PAD      160          // padded to 32*5 for a uniform unrolled loop
#define DIM        64
#define MU_PITCH   68           // DIM + 4 pad: rows 16B-aligned
#define NROWS      8192         // 512 * 16
#define ROWS_PER_BLK 32         // 16 warps x 2 rows
#define NTHR       512
#define MAIN_BLOCKS (NROWS / ROWS_PER_BLK)   // 256

#define LOG2PI_F   1.8378770664093453f
#define LN2_F      0.6931471805599453f
#define L2E_F      1.4426950408889634f
// Phi-tanh approx: Phi(x) ~= 0.5*(1+tanh(C1*x + C3*x^3))
#define PHI_C1     0.7978845608028654f
#define PHI_C3     0.03567740813712f

// ---- device scratch (static globals; no allocation) ----
__device__ float  d_partials[MAIN_BLOCKS];
__device__ unsigned int d_counter = 0;

typedef unsigned long long ull;

__device__ __forceinline__ float tanh_approx(float x) {
    float r; asm("tanh.approx.f32 %0, %1;" : "=f"(r) : "f"(x)); return r;
}
__device__ __forceinline__ float ex2_approx(float x) {
    float r; asm("ex2.approx.f32 %0, %1;" : "=f"(r) : "f"(x)); return r;
}
// f32x2 packed helpers (sm_103a)
__device__ __forceinline__ ull pk2(float a, float b) {
    ull r; asm("mov.b64 %0, {%1,%2};" : "=l"(r)
               : "r"(__float_as_uint(a)), "r"(__float_as_uint(b))); return r;
}
__device__ __forceinline__ ull dup2(float a) { return pk2(a, a); }
__device__ __forceinline__ void upk2(ull v, float& a, float& b) {
    unsigned int x, y; asm("mov.b64 {%0,%1}, %2;" : "=r"(x), "=r"(y) : "l"(v));
    a = __uint_as_float(x); b = __uint_as_float(y);
}
__device__ __forceinline__ ull add2(ull a, ull b) {
    ull r; asm("add.rn.f32x2 %0, %1, %2;" : "=l"(r) : "l"(a), "l"(b)); return r;
}
__device__ __forceinline__ ull mul2(ull a, ull b) {
    ull r; asm("mul.rn.f32x2 %0, %1, %2;" : "=l"(r) : "l"(a), "l"(b)); return r;
}
__device__ __forceinline__ ull fma2p(ull a, ull b, ull c) {
    ull r; asm("fma.rn.f32x2 %0, %1, %2, %3;" : "=l"(r) : "l"(a), "l"(b), "l"(c)); return r;
}

// ---------------------------------------------------------------------------
// SINGLE fused kernel. 32 rows/block (512 thr, 16 warps), two rows per warp.
// log2-domain hot loop: x = baseC2 + gBL + 0.5*deltaL*nu - shiftL,
// shiftL = bC2max + z2h*log2e (z2h cancels in rowres).
// Table: c4 = {k1L, recipX=recip/log2e, s, baseC2=(base-mB2/2)*log2e}, ab int.
// Diagonal pairs: k1L=0, recipX=0 -> nu=0; s=20 -> D=1.
// Slots [136,160): baseC2=-1e30 (ex2 -> 0).
// ---------------------------------------------------------------------------
__global__ __launch_bounds__(NTHR) void fused_kernel(const float* __restrict__ z,
                                                     const float* __restrict__ pi,
                                                     const float* __restrict__ mu,
                                                     float* __restrict__ out)
{
    __shared__ float  mu_t[N_K][MU_PITCH];          // transposed mu
    __shared__ float  z_s [ROWS_PER_BLK][DIM];      // 8 KB
    __shared__ float  g_gram[N_K][N_K + 1];         // Gram(mu_k, mu_j)
    __shared__ float4 c4_s[C_PAD];                  // {k1L, recipX, s, baseC2}
    __shared__ int    ab_s[C_PAD];                  // A | B<<8
    __shared__ float  rowres[ROWS_PER_BLK];
    __shared__ float  red[NTHR];
    __shared__ int    s_is_last;

    const int t = threadIdx.x;
    const int w = t >> 5;        // warp 0..15; handles rows 2w, 2w+1
    const int l = t & 31;

    // prefetch both rows' z into registers immediately
    const int row0 = blockIdx.x * ROWS_PER_BLK;
    const float* zp0 = z + (row0 + 2 * w) * DIM;
    const float za0 = zp0[l], za1 = zp0[l + 32];
    const float zb0 = zp0[DIM + l], zb1 = zp0[DIM + l + 32];

    // stage mu transposed (2 iterations at 512 threads)
    for (int i = t; i < DIM * N_K; i += NTHR) {
        const int d = i >> 4, k = i & 15;           // mu is [d][k]
        mu_t[k][d] = mu[i];
    }
    // stage this warp's z rows
    z_s[2 * w][l]          = za0;
    z_s[2 * w][l + 32]     = za1;
    z_s[2 * w + 1][l]      = zb0;
    z_s[2 * w + 1][l + 32] = zb1;
    // padding category slots
    if (t >= C_CAT && t < C_PAD) {
        c4_s[t] = make_float4(0.f, 0.f, 20.f, -1e30f);
        ab_s[t] = 0;
    }

    // warp-local softmax denominator -- only warps 0..4 (feed threads < 136)
    float lgden = 0.f;
    if (w < 5) {
        const float v0 = pi[l], v1 = pi[l + 32], v2 = pi[l + 64], v3 = pi[l + 96];
        const float v4 = (l < 8) ? pi[128 + l] : -INFINITY;
        float mx = fmaxf(fmaxf(fmaxf(v0, v1), fmaxf(v2, v3)), v4);
        #pragma unroll
        for (int o = 16; o; o >>= 1) mx = fmaxf(mx, __shfl_xor_sync(0xffffffffu, mx, o));
        float sm = __expf(v0 - mx) + __expf(v1 - mx) + __expf(v2 - mx) + __expf(v3 - mx)
                 + ((l < 8) ? __expf(v4 - mx) : 0.f);
        #pragma unroll
        for (int o = 16; o; o >>= 1) sm += __shfl_xor_sync(0xffffffffu, sm, o);
        lgden = mx + __logf(sm);
    }

    __syncthreads();                                 // mu_t ready

    // ---- Gram pass: thread c (<136) computes dot(mu_A, mu_B), one pass ----
    int Ad = 0, Bd = 0;
    if (t < C_CAT) {
        const float cf = (float)t;
        Ad = (int)floorf((33.0f - sqrtf(fmaf(-8.0f, cf, 1089.0f))) * 0.5f);
        Bd = t - ((33 - Ad) * Ad >> 1) + Ad;         // f(A) = A*(33-A)/2

        const float4* ma = (const float4*)&mu_t[Ad][0];
        const float4* mb = (const float4*)&mu_t[Bd][0];
        float a0 = 0.f, a1 = 0.f, a2 = 0.f, a3 = 0.f;
        #pragma unroll
        for (int j = 0; j < 16; ++j) {
            const float4 fa = ma[j];
            const float4 fb = mb[j];
            a0 = fmaf(fa.x, fb.x, a0); a1 = fmaf(fa.y, fb.y, a1);
            a2 = fmaf(fa.z, fb.z, a2); a3 = fmaf(fa.w, fb.w, a3);
        }
        const float g = (a0 + a1) + (a2 + a3);
        g_gram[Ad][Bd] = g;
        g_gram[Bd][Ad] = g;
    }
    __syncthreads();                                 // Gram ready

    // ---- per-category constants from Gram (log2 domain) ----
    if (t < C_CAT) {
        const float GAA = g_gram[Ad][Ad];
        const float GAB = g_gram[Ad][Bd];
        const float GBB = g_gram[Bd][Bd];
        const float invsig = (GAA - 2.0f * GAB) + GBB;
        const float lp = -32.0f * LOG2PI_F + (__ldg(&pi[t]) - lgden);

        float baseC, recipX, s, k1L;
        if (Ad == Bd) {                      // diag: inv_sig == 0 exactly
            baseC = lp - 0.5f * GBB; recipX = 0.f; s = 20.f; k1L = 0.f;
        } else {
            const float clip_is = fminf(fmaxf(invsig, 1e-12f), 1e30f);
            s      = sqrtf(clip_is);
            baseC  = lp + 0.5f * (LOG2PI_F - __logf(clip_is)) - LN2_F - 0.5f * GBB;
            recipX = (1.0f / invsig) * (1.0f / L2E_F);
            k1L    = (GBB - GAB) * L2E_F;    // dot(alpha, mu_B) * log2e
        }
        c4_s[t] = make_float4(k1L, recipX, s, baseC * L2E_F);
        ab_s[t] = Ad | (Bd << 8);
    }
    __syncthreads();                                 // constants ready

    // ---- bC2max = max_c baseC2 (per-block uniform shift component) ----
    float bmax = c4_s[l].w;
    #pragma unroll
    for (int i = 1; i < 5; ++i) bmax = fmaxf(bmax, c4_s[l + 32 * i].w);
    #pragma unroll
    for (int o = 16; o; o >>= 1) bmax = fmaxf(bmax, __shfl_xor_sync(0xffffffffu, bmax, o));
    const float bC2max = bmax;

    // 0.5*|z|^2, both rows through one butterfly
    float p0 = za0 * za0 + za1 * za1;
    float p1 = zb0 * zb0 + zb1 * zb1;
    #pragma unroll
    for (int o = 16; o; o >>= 1) {
        p0 += __shfl_xor_sync(0xffffffffu, p0, o);
        p1 += __shfl_xor_sync(0xffffffffu, p1, o);
    }

    // g-dot for both rows: mu loaded once; results prescaled by log2e
    float gvL0, gvL1;
    {
        const int k = l & 15, h = l >> 4;
        const float4* mr  = (const float4*)&mu_t[k][h * 32];
        const float4* zr0 = (const float4*)&z_s[2 * w][h * 32];
        const float4* zr1 = (const float4*)&z_s[2 * w + 1][h * 32];
        float a0 = 0.f, a1 = 0.f, a2 = 0.f, a3 = 0.f;
        float b0 = 0.f, b1 = 0.f, b2 = 0.f, b3 = 0.f;
        #pragma unroll
        for (int j = 0; j < 8; ++j) {
            const float4 mv = mr[j];
            const float4 q0 = zr0[j];
            const float4 q1 = zr1[j];
            a0 = fmaf(q0.x, mv.x, a0); a1 = fmaf(q0.y, mv.y, a1);
            a2 = fmaf(q0.z, mv.z, a2); a3 = fmaf(q0.w, mv.w, a3);
            b0 = fmaf(q1.x, mv.x, b0); b1 = fmaf(q1.y, mv.y, b1);
            b2 = fmaf(q1.z, mv.z, b2); b3 = fmaf(q1.w, mv.w, b3);
        }
        float acc0 = (a0 + a1) + (a2 + a3);
        float acc1 = (b0 + b1) + (b2 + b3);
        acc0 += __shfl_xor_sync(0xffffffffu, acc0, 16);
        acc1 += __shfl_xor_sync(0xffffffffu, acc1, 16);
        gvL0 = acc0 * L2E_F;     // lanes l, l+16 hold g_{l&15}*log2e (row 2w)
        gvL1 = acc1 * L2E_F;     // (row 2w+1)
    }

    // packed loop-invariants
    const ull NEG1  = dup2(-1.0f);
    const ull HALF2 = dup2(0.5f);
    const ull C1_2  = dup2(PHI_C1);
    const ull C3_2  = dup2(PHI_C3);
    // per-row shift: shiftL_r = bC2max + z2h_r*log2e (z2h cancels in rowres)
    const ull nSh2  = pk2(-fmaf(0.5f * p0, L2E_F, bC2max),
                          -fmaf(0.5f * p1, L2E_F, bC2max));

    // ---- hot loop: 5 categories, both rows packed in f32x2 ----
    float ss0 = 0.f, ss1 = 0.f;
    #pragma unroll
    for (int i = 0; i < 5; ++i) {
        const int c = l + 32 * i;
        const float4 q4 = c4_s[c];                  // k1L, recipX, s, baseC2
        const int ab = ab_s[c];
        const int Ai = ab & 15, Bi = (ab >> 8) & 15;
        const float gA0 = __shfl_sync(0xffffffffu, gvL0, Ai);
        const float gB0 = __shfl_sync(0xffffffffu, gvL0, Bi);
        const float gA1 = __shfl_sync(0xffffffffu, gvL1, Ai);
        const float gB1 = __shfl_sync(0xffffffffu, gvL1, Bi);

        const ull gA2 = pk2(gA0, gA1);
        const ull gB2 = pk2(gB0, gB1);
        const ull k1_2 = dup2(q4.x);
        const ull rc2  = dup2(q4.y);
        const ull s2   = dup2(q4.z);
        const ull bc2  = dup2(q4.w);

        const ull deL = add2(fma2p(gB2, NEG1, k1_2), gA2);  // deltaL
        const ull nu2 = mul2(deL, rc2);                     // true nu
        const ull bg  = add2(add2(bc2, gB2), nSh2);         // baseC2 + gBL - shift
        const ull xs  = fma2p(mul2(deL, HALF2), nu2, bg);   // exponent (log2)

        const ull ns2  = mul2(nu2, s2);
        const ull nns2 = mul2(ns2, NEG1);                   // eta2 = -nu*s
        const ull e1_2 = add2(s2, nns2);                    // eta1 = (1-nu)*s
        const ull u1_2 = mul2(e1_2, fma2p(C3_2, mul2(e1_2, e1_2), C1_2));
        const ull u2_2 = mul2(nns2, fma2p(C3_2, mul2(nns2, nns2), C1_2));

        float u1a, u1b, u2a, u2b, x0, x1;
        upk2(u1_2, u1a, u1b);
        upk2(u2_2, u2a, u2b);
        upk2(xs, x0, x1);
        const float D0 = fmaxf(tanh_approx(u1a) - tanh_approx(u2a), 2e-16f);
        const float D1 = fmaxf(tanh_approx(u1b) - tanh_approx(u2b), 2e-16f);
        ss0 = fmaf(ex2_approx(x0), D0, ss0);
        ss1 = fmaf(ex2_approx(x1), D1, ss1);
    }

    // warp sum of ss (both rows)
    #pragma unroll
    for (int o = 16; o; o >>= 1) {
        ss0 += __shfl_xor_sync(0xffffffffu, ss0, o);
        ss1 += __shfl_xor_sync(0xffffffffu, ss1, o);
    }

    // rowres = bC2max*ln2 + log(ss)   (z2h cancels exactly)
    if (l == 0) {
        const float bnat = bC2max * LN2_F;
        rowres[2 * w]     = bnat + __logf(fmaxf(ss0, 1e-37f));
        rowres[2 * w + 1] = bnat + __logf(fmaxf(ss1, 1e-37f));
    }
    __syncthreads();

    // ---- per-block partial + last-block-done finalize ----
    if (t == 0) {
        float s = 0.f;
        #pragma unroll
        for (int r = 0; r < ROWS_PER_BLK; ++r) s += rowres[r];
        d_partials[blockIdx.x] = s;
        __threadfence();
        const unsigned int ticket = atomicAdd(&d_counter, 1u);
        s_is_last = (ticket == (unsigned)(gridDim.x - 1));
    }
    __syncthreads();

    if (s_is_last) {
        float s = 0.f;
        if (t < MAIN_BLOCKS / 4) {
            const float4 v = __ldcg(((const float4*)d_partials) + t);
            s = (v.x + v.y) + (v.z + v.w);
        }
        red[t] = s; __syncthreads();
        for (int o = NTHR / 2; o; o >>= 1) { if (t < o) red[t] += red[t + o]; __syncthreads(); }
        if (t == 0) {
            out[0] = red[0] * (1.0f / (float)NROWS);
            d_counter = 0;                 // reset for next graph replay
        }
    }
}

// ---------------------------------------------------------------------------
extern "C" void kernel_launch(void* const* d_in, const int* in_sizes, int n_in,
                              void* d_out, int out_size)
{
    (void)in_sizes; (void)n_in; (void)out_size;
    const float* z  = (const float*)d_in[0];
    const float* pi = (const float*)d_in[1];
    const float* mu = (const float*)d_in[2];
    float* out = (float*)d_out;

    fused_kernel<<<MAIN_BLOCKS, NTHR>>>(z, pi, mu, out);
}